// round 3
// baseline (speedup 1.0000x reference)
#include <cuda_runtime.h>

// Output layout (floats): concatenated mips L0(2048)..L7(16), each [6,H,W,3] row-major.
#define OFF1 75497472ull
#define OFF2 94371840ull
#define OFF3 99090432ull
#define OFF4 100270080ull
#define OFF5 100564992ull
#define OFF6 100638720ull
#define OFF7 100657152ull

// Cross-block L7 handoff scratch (block pairs). Counters self-reset -> graph-replay safe.
__device__ float g_partial[6 * 16 * 16 * 2 * 3];
__device__ int   g_count[6 * 16 * 16];

// One kernel for the whole mip chain.
// Block = 16x16 threads; thread owns an 8-wide x 4-tall base region.
// Block covers 128x64 base -> 64x32 L1 -> 32x16 L2 -> 16x8 L3 -> 8x4 L4 -> 4x2 L5 -> 2x1 L6.
// L7 combines two vertically-adjacent blocks via scratch + atomic counter.
__global__ void __launch_bounds__(256) mip_kernel(const float* __restrict__ in,
                                                  float* __restrict__ out) {
    const int tx = threadIdx.x, ty = threadIdx.y;
    const int bx = blockIdx.x, by = blockIdx.y, f = blockIdx.z;

    __shared__ float s2[16][32][3];
    __shared__ float s3[8][16][3];
    __shared__ float s4[4][8][3];
    __shared__ float s5[2][4][3];
    __shared__ float s6[2][3];

    const int gx = bx * 16 + tx;   // unit = 8 base px  (0..255)
    const int gy = by * 16 + ty;   // unit = 4 base rows (0..511)

    // ---- L0 copy + L1 (two rows of 4 px) ----
    float l1r[2][12];
    #pragma unroll
    for (int rp = 0; rp < 2; rp++) {
        float sum[24];
        #pragma unroll
        for (int rr = 0; rr < 2; rr++) {
            const size_t rowoff =
                ((size_t)(f * 2048 + gy * 4 + rp * 2 + rr) * 2048 + (size_t)gx * 8) * 3;
            const float4* p = reinterpret_cast<const float4*>(in + rowoff);
            float4* q = reinterpret_cast<float4*>(out + rowoff);
            #pragma unroll
            for (int j = 0; j < 6; j++) {
                const float4 u = __ldcs(p + j);
                __stcs(q + j, u);
                if (rr == 0) {
                    sum[4 * j] = u.x; sum[4 * j + 1] = u.y;
                    sum[4 * j + 2] = u.z; sum[4 * j + 3] = u.w;
                } else {
                    sum[4 * j] += u.x; sum[4 * j + 1] += u.y;
                    sum[4 * j + 2] += u.z; sum[4 * j + 3] += u.w;
                }
            }
        }
        #pragma unroll
        for (int j = 0; j < 4; j++)
            #pragma unroll
            for (int c = 0; c < 3; c++)
                l1r[rp][3 * j + c] = 0.25f * (sum[6 * j + c] + sum[6 * j + 3 + c]);

        const size_t o1 = OFF1 + ((size_t)(f * 1024 + gy * 2 + rp) * 1024 + (size_t)gx * 4) * 3;
        float4* q1 = reinterpret_cast<float4*>(out + o1);   // gx*4*3 multiple of 12 -> 16B aligned
        __stcs(q1 + 0, make_float4(l1r[rp][0], l1r[rp][1], l1r[rp][2],  l1r[rp][3]));
        __stcs(q1 + 1, make_float4(l1r[rp][4], l1r[rp][5], l1r[rp][6],  l1r[rp][7]));
        __stcs(q1 + 2, make_float4(l1r[rp][8], l1r[rp][9], l1r[rp][10], l1r[rp][11]));
    }

    // ---- L2: 2 px per thread ----
    {
        float l2[6];
        #pragma unroll
        for (int j = 0; j < 2; j++)
            #pragma unroll
            for (int c = 0; c < 3; c++)
                l2[3 * j + c] = 0.25f * (l1r[0][6 * j + c] + l1r[0][6 * j + 3 + c] +
                                         l1r[1][6 * j + c] + l1r[1][6 * j + 3 + c]);
        const size_t o2 = OFF2 + ((size_t)(f * 512 + gy) * 512 + (size_t)gx * 2) * 3;
        float2* q2 = reinterpret_cast<float2*>(out + o2);   // 6*gx floats -> 8B aligned
        __stcs(q2 + 0, make_float2(l2[0], l2[1]));
        __stcs(q2 + 1, make_float2(l2[2], l2[3]));
        __stcs(q2 + 2, make_float2(l2[4], l2[5]));
        #pragma unroll
        for (int c = 0; c < 3; c++) {
            s2[ty][2 * tx][c]     = l2[c];
            s2[ty][2 * tx + 1][c] = l2[3 + c];
        }
    }
    __syncthreads();

    const int tid = ty * 16 + tx;

    // ---- L3: 16x8 per block (face 256) ----
    if (tid < 128) {
        const int x = tid & 15, y = tid >> 4;
        const size_t o = OFF3 + ((size_t)(f * 256 + by * 8 + y) * 256 + (size_t)(bx * 16 + x)) * 3;
        #pragma unroll
        for (int c = 0; c < 3; c++) {
            const float v = 0.25f * (s2[2 * y][2 * x][c] + s2[2 * y][2 * x + 1][c] +
                                     s2[2 * y + 1][2 * x][c] + s2[2 * y + 1][2 * x + 1][c]);
            __stcs(out + o + c, v);
            s3[y][x][c] = v;
        }
    }
    __syncthreads();

    // ---- L4: 8x4 per block (face 128) ----
    if (tid < 32) {
        const int x = tid & 7, y = tid >> 3;
        const size_t o = OFF4 + ((size_t)(f * 128 + by * 4 + y) * 128 + (size_t)(bx * 8 + x)) * 3;
        #pragma unroll
        for (int c = 0; c < 3; c++) {
            const float v = 0.25f * (s3[2 * y][2 * x][c] + s3[2 * y][2 * x + 1][c] +
                                     s3[2 * y + 1][2 * x][c] + s3[2 * y + 1][2 * x + 1][c]);
            __stcs(out + o + c, v);
            s4[y][x][c] = v;
        }
    }
    __syncthreads();

    // ---- L5: 4x2 per block (face 64) ----
    if (tid < 8) {
        const int x = tid & 3, y = tid >> 2;
        const size_t o = OFF5 + ((size_t)(f * 64 + by * 2 + y) * 64 + (size_t)(bx * 4 + x)) * 3;
        #pragma unroll
        for (int c = 0; c < 3; c++) {
            const float v = 0.25f * (s4[2 * y][2 * x][c] + s4[2 * y][2 * x + 1][c] +
                                     s4[2 * y + 1][2 * x][c] + s4[2 * y + 1][2 * x + 1][c]);
            __stcs(out + o + c, v);
            s5[y][x][c] = v;
        }
    }
    __syncthreads();

    // ---- L6: 2x1 per block (face 32) ----
    if (tid < 2) {
        const int x = tid;
        const size_t o = OFF6 + ((size_t)(f * 32 + by) * 32 + (size_t)(bx * 2 + x)) * 3;
        #pragma unroll
        for (int c = 0; c < 3; c++) {
            const float v = 0.25f * (s5[0][2 * x][c] + s5[0][2 * x + 1][c] +
                                     s5[1][2 * x][c] + s5[1][2 * x + 1][c]);
            __stcs(out + o + c, v);
            s6[x][c] = v;
        }
    }
    __syncthreads();

    // ---- L7: combine two vertically-adjacent blocks (face 16) ----
    if (tid == 0) {
        const int Y7 = by >> 1;
        const int idx = (f * 16 + bx) * 16 + Y7;           // counter index
        float* slot = g_partial + ((size_t)idx * 2 + (by & 1)) * 3;
        #pragma unroll
        for (int c = 0; c < 3; c++)
            slot[c] = s6[0][c] + s6[1][c];                 // this block's 2 L6 pixels
        __threadfence();
        const int old = atomicAdd(&g_count[idx], 1);
        if (old == 1) {                                     // second arriver combines
            __threadfence();
            const float* s0 = g_partial + (size_t)idx * 2 * 3;
            const float* s1 = s0 + 3;
            const size_t o = OFF7 + ((size_t)(f * 16 + Y7) * 16 + bx) * 3;
            #pragma unroll
            for (int c = 0; c < 3; c++)
                out[o + c] = 0.25f * (s0[c] + s1[c]);
            atomicExch(&g_count[idx], 0);                  // reset for next replay
        }
    }
}

extern "C" void kernel_launch(void* const* d_in, const int* in_sizes, int n_in,
                              void* d_out, int out_size) {
    const float* base = (const float*)d_in[0];
    float* out = (float*)d_out;
    mip_kernel<<<dim3(16, 32, 6), dim3(16, 16)>>>(base, out);
}

// round 4
// speedup vs baseline: 1.4621x; 1.4621x over previous
#include <cuda_runtime.h>

// Output layout (floats): concatenated mips L0(2048)..L7(16), each [6,H,W,3] row-major.
#define OFF1 75497472ull
#define OFF2 94371840ull
#define OFF3 99090432ull
#define OFF4 100270080ull
#define OFF5 100564992ull
#define OFF6 100638720ull
#define OFF7 100657152ull

// Cross-block L7 handoff scratch: each L7 pixel = 2x2 block group (4 quadrant slots).
// Counters self-reset after use -> safe across graph replays.
__device__ float g_partial[6 * 16 * 16 * 4 * 3];
__device__ int   g_count[6 * 16 * 16];

// Single kernel for the whole mip chain.
// Block = 16x16 threads, thread owns a 4x4 base tile.
// Block covers 64x64 base -> 32x32 L1 -> 16x16 L2 -> 8x8 L3 -> 4x4 L4 -> 2x2 L5 -> 1 L6.
// L7 (face 16): 4 blocks combine via scratch + atomic counter, fixed summation order.
__global__ void __launch_bounds__(256) mip_kernel(const float* __restrict__ in,
                                                  float* __restrict__ out) {
    const int tx = threadIdx.x, ty = threadIdx.y;
    const int bx = blockIdx.x, by = blockIdx.y, f = blockIdx.z;
    const int x2 = bx * 16 + tx;        // L2 coords (512-wide face)
    const int y2 = by * 16 + ty;

    __shared__ float s2[16][16][3];
    __shared__ float s3[8][8][3];
    __shared__ float s4[4][4][3];
    __shared__ float s5[2][2][3];

    // ---- L0 copy + L1 (process base rows in pairs; loads front-batched) ----
    const size_t row0 = ((size_t)(f * 2048 + y2 * 4) * 2048 + (size_t)x2 * 4) * 3;
    float m[2][6];                       // 2x2 L1 pixels (rgb each)
    #pragma unroll
    for (int rp = 0; rp < 2; rp++) {
        const float4* p0 = reinterpret_cast<const float4*>(in + row0 + (size_t)(2 * rp) * 6144);
        const float4* p1 = reinterpret_cast<const float4*>(in + row0 + (size_t)(2 * rp + 1) * 6144);
        const float4 a0 = __ldcs(p0 + 0), a1 = __ldcs(p0 + 1), a2 = __ldcs(p0 + 2);
        const float4 b0 = __ldcs(p1 + 0), b1 = __ldcs(p1 + 1), b2 = __ldcs(p1 + 2);

        float4* q0 = reinterpret_cast<float4*>(out + row0 + (size_t)(2 * rp) * 6144);
        float4* q1 = reinterpret_cast<float4*>(out + row0 + (size_t)(2 * rp + 1) * 6144);
        __stcs(q0 + 0, a0); __stcs(q0 + 1, a1); __stcs(q0 + 2, a2);
        __stcs(q1 + 0, b0); __stcs(q1 + 1, b1); __stcs(q1 + 2, b2);

        // Row floats: [p0.r p0.g p0.b p1.r p1.g p1.b | p2.r p2.g p2.b p3.r p3.g p3.b]
        // L1 px0 = avg(p0,p1 both rows), px1 = avg(p2,p3 both rows).
        m[rp][0] = 0.25f * ((a0.x + a0.w) + (b0.x + b0.w));
        m[rp][1] = 0.25f * ((a0.y + a1.x) + (b0.y + b1.x));
        m[rp][2] = 0.25f * ((a0.z + a1.y) + (b0.z + b1.y));
        m[rp][3] = 0.25f * ((a1.z + a2.y) + (b1.z + b2.y));
        m[rp][4] = 0.25f * ((a1.w + a2.z) + (b1.w + b2.z));
        m[rp][5] = 0.25f * ((a2.x + a2.w) + (b2.x + b2.w));

        const size_t o1 = OFF1 + ((size_t)(f * 1024 + y2 * 2 + rp) * 1024 + (size_t)x2 * 2) * 3;
        float2* q = reinterpret_cast<float2*>(out + o1);   // 6*x2 floats -> 8B aligned
        __stcs(q + 0, make_float2(m[rp][0], m[rp][1]));
        __stcs(q + 1, make_float2(m[rp][2], m[rp][3]));
        __stcs(q + 2, make_float2(m[rp][4], m[rp][5]));
    }

    // ---- L2: 1 px per thread ----
    {
        const size_t o2 = OFF2 + ((size_t)(f * 512 + y2) * 512 + x2) * 3;
        #pragma unroll
        for (int c = 0; c < 3; c++) {
            const float v = 0.25f * (m[0][c] + m[0][c + 3] + m[1][c] + m[1][c + 3]);
            __stcs(out + o2 + c, v);
            s2[ty][tx][c] = v;
        }
    }
    __syncthreads();

    const int tid = ty * 16 + tx;

    // ---- L3: 8x8 per block (face 256) ----
    if (tid < 64) {
        const int x = tid & 7, y = tid >> 3;
        const size_t o = OFF3 + ((size_t)(f * 256 + by * 8 + y) * 256 + (size_t)(bx * 8 + x)) * 3;
        #pragma unroll
        for (int c = 0; c < 3; c++) {
            const float v = 0.25f * (s2[2 * y][2 * x][c] + s2[2 * y][2 * x + 1][c] +
                                     s2[2 * y + 1][2 * x][c] + s2[2 * y + 1][2 * x + 1][c]);
            __stcs(out + o + c, v);
            s3[y][x][c] = v;
        }
    }
    __syncthreads();

    // ---- L4: 4x4 per block (face 128) ----
    if (tid < 16) {
        const int x = tid & 3, y = tid >> 2;
        const size_t o = OFF4 + ((size_t)(f * 128 + by * 4 + y) * 128 + (size_t)(bx * 4 + x)) * 3;
        #pragma unroll
        for (int c = 0; c < 3; c++) {
            const float v = 0.25f * (s3[2 * y][2 * x][c] + s3[2 * y][2 * x + 1][c] +
                                     s3[2 * y + 1][2 * x][c] + s3[2 * y + 1][2 * x + 1][c]);
            __stcs(out + o + c, v);
            s4[y][x][c] = v;
        }
    }
    __syncthreads();

    // ---- L5: 2x2 per block (face 64) ----
    if (tid < 4) {
        const int x = tid & 1, y = tid >> 1;
        const size_t o = OFF5 + ((size_t)(f * 64 + by * 2 + y) * 64 + (size_t)(bx * 2 + x)) * 3;
        #pragma unroll
        for (int c = 0; c < 3; c++) {
            const float v = 0.25f * (s4[2 * y][2 * x][c] + s4[2 * y][2 * x + 1][c] +
                                     s4[2 * y + 1][2 * x][c] + s4[2 * y + 1][2 * x + 1][c]);
            __stcs(out + o + c, v);
            s5[y][x][c] = v;
        }
    }
    __syncthreads();

    // ---- L6: 1 px per block (face 32) + L7 handoff (face 16) ----
    if (tid == 0) {
        float v6[3];
        const size_t o6 = OFF6 + ((size_t)(f * 32 + by) * 32 + bx) * 3;
        #pragma unroll
        for (int c = 0; c < 3; c++) {
            v6[c] = 0.25f * (s5[0][0][c] + s5[0][1][c] + s5[1][0][c] + s5[1][1][c]);
            __stcs(out + o6 + c, v6[c]);
        }

        // L7: each pixel = 2x2 block group; quadrant q, fixed combine order.
        const int X7 = bx >> 1, Y7 = by >> 1;
        const int q = (by & 1) * 2 + (bx & 1);
        const int idx = (f * 16 + Y7) * 16 + X7;
        float* slot = g_partial + ((size_t)idx * 4 + q) * 3;
        slot[0] = v6[0]; slot[1] = v6[1]; slot[2] = v6[2];
        __threadfence();
        const int old = atomicAdd(&g_count[idx], 1);
        if (old == 3) {                                    // last arriver combines
            __threadfence();
            const float* s = g_partial + (size_t)idx * 4 * 3;
            const size_t o7 = OFF7 + ((size_t)(f * 16 + Y7) * 16 + X7) * 3;
            #pragma unroll
            for (int c = 0; c < 3; c++)
                out[o7 + c] = 0.25f * ((s[c] + s[3 + c]) + (s[6 + c] + s[9 + c]));
            atomicExch(&g_count[idx], 0);                  // reset for next replay
        }
    }
}

extern "C" void kernel_launch(void* const* d_in, const int* in_sizes, int n_in,
                              void* d_out, int out_size) {
    const float* base = (const float*)d_in[0];
    float* out = (float*)d_out;
    mip_kernel<<<dim3(32, 32, 6), dim3(16, 16)>>>(base, out);
}

// round 5
// speedup vs baseline: 1.7435x; 1.1924x over previous
#include <cuda_runtime.h>

// Output layout (floats): concatenated mips L0(2048)..L7(16), each [6,H,W,3] row-major.
#define OFF1 75497472ull
#define OFF2 94371840ull
#define OFF3 99090432ull
#define OFF4 100270080ull
#define OFF5 100564992ull
#define OFF6 100638720ull
#define OFF7 100657152ull

// L7 cross-block handoff (2 vertically-adjacent blocks per L7 pixel).
// Counters self-reset -> graph-replay safe. Fixed combine order -> deterministic.
__device__ float g_partial[6 * 16 * 16 * 2 * 3];
__device__ int   g_count[6 * 16 * 16];

// Single kernel, fully coalesced main streams.
// Block = 256 threads (8 warps), tile = 128 wide x 64 tall base px. Grid (16,32,6).
// Warp w owns tile rows [8w, 8w+8): 4 row-pairs -> 4 L1 rows -> 2 L2 rows.
// Per row-pair: 6 coalesced LDG.128 -> 6 coalesced STG.128 (L0 copy) -> STS ->
// syncwarp -> pixel-aligned LDS.128 -> L1 (2 px/lane) -> L2 accumulation.
// L2 tile (32x16) lands in smem; tail L3..L6 reduced block-locally; L7 via scratch.
__global__ void __launch_bounds__(256) mip_kernel(const float* __restrict__ in,
                                                  float* __restrict__ out) {
    const int tid = threadIdx.x;
    const int w = tid >> 5, l = tid & 31;
    const int bx = blockIdx.x, by = blockIdx.y, f = blockIdx.z;

    __shared__ float4 buf[8][192];        // per-warp staging: 2 rows x 96 f4
    __shared__ float s2[16][32][3];       // L2 tile
    __shared__ float s3[8][16][3];
    __shared__ float s4[4][8][3];
    __shared__ float s5[2][4][3];
    __shared__ float s6[2][3];

    float acc[3];

    #pragma unroll
    for (int rp = 0; rp < 4; rp++) {
        const int r0 = by * 64 + w * 8 + 2 * rp;      // global base row
        const size_t off0 = ((size_t)(f * 2048 + r0) * 2048 + (size_t)bx * 128) * 3;
        const float4* in0 = reinterpret_cast<const float4*>(in + off0);
        const float4* in1 = reinterpret_cast<const float4*>(in + off0 + 6144);
        float4* o0 = reinterpret_cast<float4*>(out + off0);
        float4* o1p = reinterpret_cast<float4*>(out + off0 + 6144);

        // coalesced loads (front-batched), coalesced copy stores, stage to smem
        float4 A0 = __ldcs(in0 + l), A1 = __ldcs(in0 + 32 + l), A2 = __ldcs(in0 + 64 + l);
        float4 B0 = __ldcs(in1 + l), B1 = __ldcs(in1 + 32 + l), B2 = __ldcs(in1 + 64 + l);
        __stcs(o0 + l, A0);       __stcs(o0 + 32 + l, A1);  __stcs(o0 + 64 + l, A2);
        __stcs(o1p + l, B0);      __stcs(o1p + 32 + l, B1); __stcs(o1p + 64 + l, B2);
        buf[w][l] = A0;       buf[w][32 + l] = A1;      buf[w][64 + l] = A2;
        buf[w][96 + l] = B0;  buf[w][128 + l] = B1;     buf[w][160 + l] = B2;
        __syncwarp();

        // pixel-aligned views: lane l owns base px [4l, 4l+4) of both rows
        const float4 Ra0 = buf[w][3 * l], Ra1 = buf[w][3 * l + 1], Ra2 = buf[w][3 * l + 2];
        const float4 Rb0 = buf[w][96 + 3 * l], Rb1 = buf[w][97 + 3 * l], Rb2 = buf[w][98 + 3 * l];
        const float r0f[12] = {Ra0.x, Ra0.y, Ra0.z, Ra0.w, Ra1.x, Ra1.y,
                               Ra1.z, Ra1.w, Ra2.x, Ra2.y, Ra2.z, Ra2.w};
        const float r1f[12] = {Rb0.x, Rb0.y, Rb0.z, Rb0.w, Rb1.x, Rb1.y,
                               Rb1.z, Rb1.w, Rb2.x, Rb2.y, Rb2.z, Rb2.w};

        // L1: 2 adjacent px per lane
        float l1a[3], l1b[3];
        #pragma unroll
        for (int c = 0; c < 3; c++) {
            l1a[c] = 0.25f * ((r0f[c] + r0f[c + 3]) + (r1f[c] + r1f[c + 3]));
            l1b[c] = 0.25f * ((r0f[c + 6] + r0f[c + 9]) + (r1f[c + 6] + r1f[c + 9]));
        }
        const int y1 = by * 32 + w * 4 + rp;
        const size_t o1 = OFF1 + ((size_t)(f * 1024 + y1) * 1024 + (size_t)bx * 64) * 3
                        + (size_t)(6 * l);
        float2* q1 = reinterpret_cast<float2*>(out + o1);
        __stcs(q1 + 0, make_float2(l1a[0], l1a[1]));
        __stcs(q1 + 1, make_float2(l1a[2], l1b[0]));
        __stcs(q1 + 2, make_float2(l1b[1], l1b[2]));

        // L2: combine across the two L1 rows of this pair-of-pairs
        if ((rp & 1) == 0) {
            #pragma unroll
            for (int c = 0; c < 3; c++) acc[c] = l1a[c] + l1b[c];
        } else {
            const int y2 = by * 16 + w * 2 + (rp >> 1);
            const size_t o2 = OFF2 + ((size_t)(f * 512 + y2) * 512 + (size_t)bx * 32) * 3
                            + (size_t)(3 * l);
            const int sy = w * 2 + (rp >> 1);
            #pragma unroll
            for (int c = 0; c < 3; c++) {
                const float v = 0.25f * (acc[c] + (l1a[c] + l1b[c]));
                __stcs(out + o2 + c, v);
                s2[sy][l][c] = v;
            }
        }
        __syncwarp();    // protect buf reuse next iteration
    }
    __syncthreads();

    // ---- L3: 16x8 per block (face 256) ----
    if (tid < 128) {
        const int x = tid & 15, y = tid >> 4;
        const size_t o = OFF3 + ((size_t)(f * 256 + by * 8 + y) * 256 + (size_t)(bx * 16 + x)) * 3;
        #pragma unroll
        for (int c = 0; c < 3; c++) {
            const float v = 0.25f * (s2[2 * y][2 * x][c] + s2[2 * y][2 * x + 1][c] +
                                     s2[2 * y + 1][2 * x][c] + s2[2 * y + 1][2 * x + 1][c]);
            __stcs(out + o + c, v);
            s3[y][x][c] = v;
        }
    }
    __syncthreads();

    // ---- L4: 8x4 per block (face 128) ----
    if (tid < 32) {
        const int x = tid & 7, y = tid >> 3;
        const size_t o = OFF4 + ((size_t)(f * 128 + by * 4 + y) * 128 + (size_t)(bx * 8 + x)) * 3;
        #pragma unroll
        for (int c = 0; c < 3; c++) {
            const float v = 0.25f * (s3[2 * y][2 * x][c] + s3[2 * y][2 * x + 1][c] +
                                     s3[2 * y + 1][2 * x][c] + s3[2 * y + 1][2 * x + 1][c]);
            __stcs(out + o + c, v);
            s4[y][x][c] = v;
        }
    }
    __syncthreads();

    // ---- L5: 4x2 per block (face 64) ----
    if (tid < 8) {
        const int x = tid & 3, y = tid >> 2;
        const size_t o = OFF5 + ((size_t)(f * 64 + by * 2 + y) * 64 + (size_t)(bx * 4 + x)) * 3;
        #pragma unroll
        for (int c = 0; c < 3; c++) {
            const float v = 0.25f * (s4[2 * y][2 * x][c] + s4[2 * y][2 * x + 1][c] +
                                     s4[2 * y + 1][2 * x][c] + s4[2 * y + 1][2 * x + 1][c]);
            __stcs(out + o + c, v);
            s5[y][x][c] = v;
        }
    }
    __syncthreads();

    // ---- L6: 2x1 per block (face 32) ----
    if (tid < 2) {
        const int x = tid;
        const size_t o = OFF6 + ((size_t)(f * 32 + by) * 32 + (size_t)(bx * 2 + x)) * 3;
        #pragma unroll
        for (int c = 0; c < 3; c++) {
            const float v = 0.25f * (s5[0][2 * x][c] + s5[0][2 * x + 1][c] +
                                     s5[1][2 * x][c] + s5[1][2 * x + 1][c]);
            __stcs(out + o + c, v);
            s6[x][c] = v;
        }
    }
    __syncthreads();

    // ---- L7: 2-block vertical combine (face 16) ----
    if (tid == 0) {
        const int Y7 = by >> 1;
        const int idx = (f * 16 + Y7) * 16 + bx;
        float* slot = g_partial + ((size_t)idx * 2 + (by & 1)) * 3;
        #pragma unroll
        for (int c = 0; c < 3; c++)
            slot[c] = s6[0][c] + s6[1][c];
        __threadfence();
        const int old = atomicAdd(&g_count[idx], 1);
        if (old == 1) {
            __threadfence();
            const float* s = g_partial + (size_t)idx * 2 * 3;
            const size_t o7 = OFF7 + ((size_t)(f * 16 + Y7) * 16 + bx) * 3;
            #pragma unroll
            for (int c = 0; c < 3; c++)
                out[o7 + c] = 0.25f * (s[c] + s[3 + c]);
            atomicExch(&g_count[idx], 0);
        }
    }
}

extern "C" void kernel_launch(void* const* d_in, const int* in_sizes, int n_in,
                              void* d_out, int out_size) {
    const float* base = (const float*)d_in[0];
    float* out = (float*)d_out;
    mip_kernel<<<dim3(16, 32, 6), 256>>>(base, out);
}